// round 6
// baseline (speedup 1.0000x reference)
#include <cuda_runtime.h>
#include <math.h>

#define BB    2
#define NQQ   900
#define EE    256
#define NH    8
#define HDIM  32
#define HWK   4096
#define RPEH  512
#define LOG2E_F 1.4426950408889634f
#define QSCALE_F 0.17677669529663687f

// Scratch (no cudaMalloc allowed). g_qT padded: attn reads past row ends on the
// last (partially valid) query tile.
__device__ float g_qT[BB * NH * HDIM * NQQ + 1024]; // [(b*8+h)*32+d][900]
__device__ float g_kT[BB * NH * HDIM * HWK];        // [(b*8+h)*32+d][4096]
__device__ float g_v [BB * HWK * EE];
__device__ float g_rx[BB * NH * NQQ * 64];          // [bh][q][w], pre-scaled by log2e
__device__ float g_ryT[BB * NH * 64 * NQQ];         // [bh][c][q]
__device__ float g_att[BB * NQQ * EE];

typedef unsigned long long u64;

__device__ __forceinline__ float fexp2(float x) {
    float y; asm("ex2.approx.ftz.f32 %0, %1;" : "=f"(y) : "f"(x)); return y;
}
__device__ __forceinline__ u64 ffma2(u64 a, u64 b, u64 c) {
    u64 d; asm("fma.rn.f32x2 %0, %1, %2, %3;" : "=l"(d) : "l"(a), "l"(b), "l"(c)); return d;
}
__device__ __forceinline__ u64 fmul2(u64 a, u64 b) {
    u64 d; asm("mul.rn.f32x2 %0, %1, %2;" : "=l"(d) : "l"(a), "l"(b)); return d;
}
__device__ __forceinline__ u64 fadd2(u64 a, u64 b) {
    u64 d; asm("add.rn.f32x2 %0, %1, %2;" : "=l"(d) : "l"(a), "l"(b)); return d;
}
__device__ __forceinline__ u64 dup2(float x) {
    u64 r; asm("mov.b64 %0, {%1, %1};" : "=l"(r) : "f"(x)); return r;
}
__device__ __forceinline__ u64 pack2(float lo, float hi) {
    u64 r; asm("mov.b64 %0, {%1, %2};" : "=l"(r) : "f"(lo), "f"(hi)); return r;
}
__device__ __forceinline__ float2 unpk2(u64 v) {
    float2 r; asm("mov.b64 {%0, %1}, %2;" : "=f"(r.x), "=f"(r.y) : "l"(v)); return r;
}
__device__ __forceinline__ float logdelta(float d) {
    float l = log2f(fabsf(d) + 1.0f) * (1.0f / 3.0f);
    return copysignf(l, d);
}

// ---------------------------------------------------------------------------
// C = alpha*(A[M,256] @ W[256,256] + bias).
// TMODE 0: row-major. TMODE 1: per-head transposed:
//   C[((m/plane)*8 + n/32)*32 + n%32][m%plane]
// ---------------------------------------------------------------------------
template<int TMODE>
__global__ void gemm_bias_kernel(const float* __restrict__ A,
                                 const float* __restrict__ Wm,
                                 const float* __restrict__ bias,
                                 float* __restrict__ C,
                                 int M, int plane, float alpha)
{
    __shared__ __align__(16) float As[16][64];
    __shared__ __align__(16) float Ws[16][64];

    int tid = threadIdx.x;
    int m0 = blockIdx.x * 64;
    int n0 = blockIdx.y * 64;
    int tm = tid >> 4, tn = tid & 15;
    int lrow = tid >> 2, lkq = tid & 3;
    int wkk = tid >> 4, wnq = tid & 15;

    u64 acc2[4][2] = {};

    for (int k0 = 0; k0 < 256; k0 += 16) {
        float4 av = make_float4(0.f, 0.f, 0.f, 0.f);
        int m = m0 + lrow;
        if (m < M) av = *(const float4*)&A[m * 256 + k0 + 4 * lkq];
        As[4 * lkq + 0][lrow] = av.x;
        As[4 * lkq + 1][lrow] = av.y;
        As[4 * lkq + 2][lrow] = av.z;
        As[4 * lkq + 3][lrow] = av.w;
        *(float4*)&Ws[wkk][4 * wnq] =
            *(const float4*)&Wm[(k0 + wkk) * 256 + n0 + 4 * wnq];
        __syncthreads();

        #pragma unroll
        for (int kk = 0; kk < 16; kk++) {
            float4 a = *(const float4*)&As[kk][4 * tm];
            ulonglong2 w = *(const ulonglong2*)&Ws[kk][4 * tn];
            float ar[4] = {a.x, a.y, a.z, a.w};
            #pragma unroll
            for (int i = 0; i < 4; i++) {
                u64 ad = dup2(ar[i]);
                acc2[i][0] = ffma2(ad, w.x, acc2[i][0]);
                acc2[i][1] = ffma2(ad, w.y, acc2[i][1]);
            }
        }
        __syncthreads();
    }

    float4 bv = *(const float4*)&bias[n0 + 4 * tn];
    float o[4][4];
    #pragma unroll
    for (int i = 0; i < 4; i++) {
        float2 lo = unpk2(acc2[i][0]);
        float2 hi = unpk2(acc2[i][1]);
        o[i][0] = alpha * (lo.x + bv.x);
        o[i][1] = alpha * (lo.y + bv.y);
        o[i][2] = alpha * (hi.x + bv.z);
        o[i][3] = alpha * (hi.y + bv.w);
    }

    if (TMODE == 0) {
        #pragma unroll
        for (int i = 0; i < 4; i++) {
            int m = m0 + 4 * tm + i;
            if (m < M)
                *(float4*)&C[m * 256 + n0 + 4 * tn] =
                    make_float4(o[i][0], o[i][1], o[i][2], o[i][3]);
        }
    } else {
        __shared__ float Ts[64][65];
        #pragma unroll
        for (int i = 0; i < 4; i++)
            #pragma unroll
            for (int j = 0; j < 4; j++)
                Ts[4 * tn + j][4 * tm + i] = o[i][j];
        __syncthreads();
        for (int idx = tid; idx < 4096; idx += 256) {
            int ml = idx & 63, nl = idx >> 6;
            int m = m0 + ml;
            if (m < M) {
                int bq = m / plane;
                int mm = m - bq * plane;
                int n = n0 + nl;
                int row = (bq * NH + (n >> 5)) * 32 + (n & 31);
                C[(long long)row * plane + mm] = Ts[nl][ml];
            }
        }
    }
}

// ---------------------------------------------------------------------------
// RPE MLP (unchanged from R4)
// ---------------------------------------------------------------------------
__global__ void rpe_kernel(const float* __restrict__ refp,
                           const float* __restrict__ W1x, const float* __restrict__ b1x,
                           const float* __restrict__ W2x,
                           const float* __restrict__ W1y, const float* __restrict__ b1y,
                           const float* __restrict__ W2y)
{
    __shared__ __align__(16) float2 sW1[2][RPEH];
    __shared__ __align__(16) float sb1[2][RPEH];
    __shared__ __align__(16) float sW2[2][RPEH * 8];

    int tid = threadIdx.x;
    for (int i = tid; i < RPEH; i += 256) {
        sW1[0][i] = make_float2(W1x[i], W1x[RPEH + i]);  sb1[0][i] = b1x[i];
        sW1[1][i] = make_float2(W1y[i], W1y[RPEH + i]);  sb1[1][i] = b1y[i];
    }
    for (int i = tid; i < RPEH * 8; i += 256) {
        sW2[0][i] = W2x[i];
        sW2[1][i] = W2y[i];
    }
    __syncthreads();

    int bq = blockIdx.x * 4 + (tid >> 6);
    int b = bq / NQQ, q = bq - b * NQQ;
    float4 r = *(const float4*)&refp[bq * 4];
    int axis = (tid >> 5) & 1;
    int lane = tid & 31;

    float ctr = axis ? r.y : r.x;
    float sz  = axis ? r.w : r.z;
    float lo = (ctr - 0.5f * sz) * 1024.0f;
    float hi = (ctr + 0.5f * sz) * 1024.0f;
    float posA = (lane + 0.5f) * 16.0f;
    float posB = (lane + 32.5f) * 16.0f;
    float d1a = logdelta(lo - posA), d2a = logdelta(hi - posA);
    float d1b = logdelta(lo - posB), d2b = logdelta(hi - posB);

    const float2* w1 = sW1[axis];
    const float* bb = sb1[axis];
    const float* w2 = sW2[axis];

    u64 a0[4] = {}, a1[4] = {};
    #pragma unroll 4
    for (int hh = 0; hh < RPEH; hh++) {
        float2 w = w1[hh];
        float bvf = bb[hh];
        float v0 = fmaxf(fmaf(d1a, w.x, fmaf(d2a, w.y, bvf)), 0.0f);
        float v1 = fmaxf(fmaf(d1b, w.x, fmaf(d2b, w.y, bvf)), 0.0f);
        u64 v0d = dup2(v0), v1d = dup2(v1);
        ulonglong2 wlo = *(const ulonglong2*)&w2[hh * 8];
        ulonglong2 whi = *(const ulonglong2*)&w2[hh * 8 + 4];
        a0[0] = ffma2(v0d, wlo.x, a0[0]);  a0[1] = ffma2(v0d, wlo.y, a0[1]);
        a0[2] = ffma2(v0d, whi.x, a0[2]);  a0[3] = ffma2(v0d, whi.y, a0[3]);
        a1[0] = ffma2(v1d, wlo.x, a1[0]);  a1[1] = ffma2(v1d, wlo.y, a1[1]);
        a1[2] = ffma2(v1d, whi.x, a1[2]);  a1[3] = ffma2(v1d, whi.y, a1[3]);
    }

    float o0[8], o1[8];
    #pragma unroll
    for (int c = 0; c < 4; c++) {
        float2 x0 = unpk2(a0[c]); float2 x1 = unpk2(a1[c]);
        o0[2*c] = x0.x * LOG2E_F;  o0[2*c+1] = x0.y * LOG2E_F;
        o1[2*c] = x1.x * LOG2E_F;  o1[2*c+1] = x1.y * LOG2E_F;
    }
    long long bh = (long long)b * NH;
    #pragma unroll
    for (int hd = 0; hd < 8; hd++) {
        if (axis == 0) {
            g_rx[((bh + hd) * NQQ + q) * 64 + lane]      = o0[hd];
            g_rx[((bh + hd) * NQQ + q) * 64 + lane + 32] = o1[hd];
        } else {
            g_ryT[((bh + hd) * 64 + lane)      * NQQ + q] = o0[hd];
            g_ryT[((bh + hd) * 64 + lane + 32) * NQQ + q] = o1[hd];
        }
    }
}

// ---------------------------------------------------------------------------
// Fused attention v2:
//  grid (8 qtiles x 8 heads x 2 batch) = 128 blocks, 128 threads.
//  Q tile = 128 queries; chunk = 64 keys (one grid row -> scalar ry per q).
//  GEMM1: per-thread 8q x 8k, accumulators pair along q; K pre-duplicated in
//  smem so FFMA2 needs no MOV dup. Softmax entirely in registers (shfl over
//  the 8-lane k-group); m/l/scale stay in registers (same q-group owns the
//  same queries in GEMM1 and GEMM2 mappings). GEMM2: 8q x 4d, V pre-dup'd.
//  2 barriers per chunk. K single-buffered, V/ry double-buffered.
// ---------------------------------------------------------------------------
#define OFF_Q    0          // 32*128
#define OFF_KD   4096       // 32*132
#define OFF_VD   8320       // 2*64*68
#define OFF_ST   17024      // 64*132
#define OFF_RX   25472      // 64*132
#define OFF_RY   33920      // 128
#define ATTN_SMF 34048

__device__ __forceinline__ void ldK(const float* kbp, int k0, int tid, float4 r[4]) {
    int fd = tid >> 2, seg = (tid & 3) * 16;
    #pragma unroll
    for (int t = 0; t < 4; t++)
        r[t] = *(const float4*)&kbp[fd * HWK + k0 + seg + 4 * t];
}
__device__ __forceinline__ void stK(float* Kd, int tid, const float4 r[4]) {
    int fd = tid >> 2, seg = (tid & 3) * 16;
    #pragma unroll
    for (int t = 0; t < 4; t++) {
        float4 a = r[t];
        *(float4*)&Kd[fd * 132 + 2 * (seg + 4 * t)]     = make_float4(a.x, a.x, a.y, a.y);
        *(float4*)&Kd[fd * 132 + 2 * (seg + 4 * t) + 4] = make_float4(a.z, a.z, a.w, a.w);
    }
}
__device__ __forceinline__ void ldV(const float* vbp, int k0, int tid, float4 r[4]) {
    int fkr = tid >> 1, half = tid & 1;
    #pragma unroll
    for (int t = 0; t < 4; t++)
        r[t] = *(const float4*)&vbp[(k0 + fkr) * EE + half * 16 + 4 * t];
}
__device__ __forceinline__ void stV(float* Vd, int tid, const float4 r[4]) {
    int fkr = tid >> 1, half = tid & 1;
    #pragma unroll
    for (int t = 0; t < 4; t++) {
        float4 a = r[t];
        *(float4*)&Vd[fkr * 68 + 2 * (half * 16 + 4 * t)]     = make_float4(a.x, a.x, a.y, a.y);
        *(float4*)&Vd[fkr * 68 + 2 * (half * 16 + 4 * t) + 4] = make_float4(a.z, a.z, a.w, a.w);
    }
}

__global__ void __launch_bounds__(128, 1) attn_kernel(float* __restrict__ outp)
{
    extern __shared__ __align__(16) float sm[];
    float* QsT = sm + OFF_Q;    // [32 d][128 q]
    float* Kd  = sm + OFF_KD;   // [32 d][132] (64 k duplicated pairs)
    float* Vd  = sm + OFF_VD;   // 2 x [64 k][68] (32 d duplicated)
    float* ST  = sm + OFF_ST;   // [64 k][132]  (P, pairs along q)
    float* rxT = sm + OFF_RX;   // [64 w][132]
    float* ryc = sm + OFF_RY;   // [128]

    int tid = threadIdx.x;
    int qt = blockIdx.x, h = blockIdx.y, b = blockIdx.z;
    int q0 = qt * 128;
    int tq = tid >> 3, tk = tid & 7;
    int q0t = tq * 8;
    long long bh = (long long)b * NH + h;
    const float* kbp = g_kT + bh * 32 * HWK;
    const float* vbp = g_v + (long long)b * HWK * EE + h * HDIM;
    const float* ryp = g_ryT + bh * 64 * NQQ;
    int ryq = min(q0 + tid, NQQ - 1);

    // ---- Q fill (coalesced, conflict-free) ----
    {
        const float* qb = g_qT + bh * 32 * NQQ;
        int dbase = tid >> 4;
        int q4 = (tid & 15) * 8;
        #pragma unroll
        for (int rr = 0; rr < 4; rr++) {
            int d = dbase + 8 * rr;
            float4 a  = *(const float4*)&qb[d * NQQ + q0 + q4];
            float4 a2 = *(const float4*)&qb[d * NQQ + q0 + q4 + 4];
            *(float4*)&QsT[d * 128 + q4] = a;
            *(float4*)&QsT[d * 128 + q4 + 4] = a2;
        }
    }
    // ---- rx fill, transposed to [w][q] ----
    {
        const float* rxb = g_rx + bh * NQQ * 64;
        for (int idx = tid; idx < 128 * 16; idx += 128) {
            int q = idx >> 4, w4 = (idx & 15) * 4;
            int qg = min(q0 + q, NQQ - 1);
            float4 v = *(const float4*)&rxb[qg * 64 + w4];
            rxT[(w4 + 0) * 132 + q] = v.x;
            rxT[(w4 + 1) * 132 + q] = v.y;
            rxT[(w4 + 2) * 132 + q] = v.z;
            rxT[(w4 + 3) * 132 + q] = v.w;
        }
    }
    // ---- chunk 0: K, V(buf0), ry ----
    {
        float4 kr[4], vr[4];
        ldK(kbp, 0, tid, kr);
        ldV(vbp, 0, tid, vr);
        float ry0 = ryp[ryq];
        stK(Kd, tid, kr);
        stV(Vd, tid, vr);
        ryc[tid] = ry0;
    }
    __syncthreads();

    float m_prev[8], l_acc[8];
    #pragma unroll
    for (int r = 0; r < 8; r++) { m_prev[r] = -1e30f; l_acc[r] = 0.0f; }
    u64 o2[4][4] = {};

    for (int ch = 0; ch < 64; ch++) {
        int buf = ch & 1;
        const float* Vc = Vd + buf * (64 * 68);

        // ---- GEMM1: s2[qp][j], pairs along q; j -> k = (j>>1)*16 + 2*tk + (j&1)
        u64 s2[4][8] = {};
        #pragma unroll 4
        for (int kk = 0; kk < 32; kk++) {
            ulonglong2 qa = *(const ulonglong2*)&QsT[kk * 128 + q0t];
            ulonglong2 qb2 = *(const ulonglong2*)&QsT[kk * 128 + q0t + 4];
            u64 qp[4] = {qa.x, qa.y, qb2.x, qb2.y};
            #pragma unroll
            for (int L = 0; L < 4; L++) {
                ulonglong2 kv = *(const ulonglong2*)&Kd[kk * 132 + L * 32 + tk * 4];
                #pragma unroll
                for (int i = 0; i < 4; i++) {
                    s2[i][2 * L]     = ffma2(qp[i], kv.x, s2[i][2 * L]);
                    s2[i][2 * L + 1] = ffma2(qp[i], kv.y, s2[i][2 * L + 1]);
                }
            }
        }

        // ---- bias add (ry + rx), still packed ----
        {
            ulonglong2 rya = *(const ulonglong2*)&ryc[q0t];
            ulonglong2 ryb2 = *(const ulonglong2*)&ryc[q0t + 4];
            u64 ryv[4] = {rya.x, rya.y, ryb2.x, ryb2.y};
            #pragma unroll
            for (int j = 0; j < 8; j++) {
                int w = (j >> 1) * 16 + 2 * tk + (j & 1);
                ulonglong2 ra = *(const ulonglong2*)&rxT[w * 132 + q0t];
                ulonglong2 rb = *(const ulonglong2*)&rxT[w * 132 + q0t + 4];
                u64 rv[4] = {ra.x, ra.y, rb.x, rb.y};
                #pragma unroll
                for (int i = 0; i < 4; i++)
                    s2[i][j] = fadd2(s2[i][j], fadd2(rv[i], ryv[i]));
            }
        }

        // ---- register softmax ----
        float s[8][8];
        #pragma unroll
        for (int i = 0; i < 4; i++)
            #pragma unroll
            for (int j = 0; j < 8; j++) {
                float2 v = unpk2(s2[i][j]);
                s[2 * i][j] = v.x;
                s[2 * i + 1][j] = v.y;
            }
        float mx[8], sum[8], scl[8];
        #pragma unroll
        for (int r = 0; r < 8; r++) {
            float m = s[r][0];
            #pragma unroll
            for (int j = 1; j < 8; j++) m = fmaxf(m, s[r][j]);
            mx[r] = m;
        }
        #pragma unroll
        for (int d = 1; d < 8; d <<= 1)
            #pragma unroll
            for (int r = 0; r < 8; r++)
                mx[r] = fmaxf(mx[r], __shfl_xor_sync(0xffffffffu, mx[r], d));
        #pragma unroll
        for (int r = 0; r < 8; r++) {
            float mn = fmaxf(m_prev[r], mx[r]);
            float sm_ = 0.0f;
            #pragma unroll
            for (int j = 0; j < 8; j++) {
                float p = fexp2(s[r][j] - mn);
                s[r][j] = p;
                sm_ += p;
            }
            sum[r] = sm_;
            scl[r] = fexp2(m_prev[r] - mn);
            m_prev[r] = mn;
        }
        #pragma unroll
        for (int d = 1; d < 8; d <<= 1)
            #pragma unroll
            for (int r = 0; r < 8; r++)
                sum[r] += __shfl_xor_sync(0xffffffffu, sum[r], d);
        #pragma unroll
        for (int r = 0; r < 8; r++)
            l_acc[r] = l_acc[r] * scl[r] + sum[r];

        // ---- P store: ST[k][q] ----
        #pragma unroll
        for (int j = 0; j < 8; j++) {
            int k = (j >> 1) * 16 + 2 * tk + (j & 1);
            *(float4*)&ST[k * 132 + q0t] =
                make_float4(s[0][j], s[1][j], s[2][j], s[3][j]);
            *(float4*)&ST[k * 132 + q0t + 4] =
                make_float4(s[4][j], s[5][j], s[6][j], s[7][j]);
        }
        __syncthreads();

        // ---- prefetch next chunk (LDG before GEMM2, STS after) ----
        float4 kr[4], vr[4]; float ryr = 0.0f;
        if (ch < 63) {
            int k0n = (ch + 1) * 64;
            ldK(kbp, k0n, tid, kr);
            ldV(vbp, k0n, tid, vr);
            ryr = ryp[(ch + 1) * NQQ + ryq];
        }

        // ---- GEMM2: o2[qp][d] (pairs along q, V dup'd) ----
        {
            #pragma unroll
            for (int i = 0; i < 4; i++) {
                u64 sp = pack2(scl[2 * i], scl[2 * i + 1]);
                #pragma unroll
                for (int d = 0; d < 4; d++)
                    o2[i][d] = fmul2(o2[i][d], sp);
            }
            #pragma unroll 8
            for (int kk = 0; kk < 64; kk++) {
                ulonglong2 pa = *(const ulonglong2*)&ST[kk * 132 + q0t];
                ulonglong2 pb = *(const ulonglong2*)&ST[kk * 132 + q0t + 4];
                u64 pp[4] = {pa.x, pa.y, pb.x, pb.y};
                ulonglong2 va = *(const ulonglong2*)&Vc[kk * 68 + tk * 8];
                ulonglong2 vb2 = *(const ulonglong2*)&Vc[kk * 68 + tk * 8 + 4];
                u64 vd[4] = {va.x, va.y, vb2.x, vb2.y};
                #pragma unroll
                for (int i = 0; i < 4; i++) {
                    o2[i][0] = ffma2(pp[i], vd[0], o2[i][0]);
                    o2[i][1] = ffma2(pp[i], vd[1], o2[i][1]);
                    o2[i][2] = ffma2(pp[i], vd[2], o2[i][2]);
                    o2[i][3] = ffma2(pp[i], vd[3], o2[i][3]);
                }
            }
        }

        // ---- store prefetched chunk ----
        if (ch < 63) {
            stK(Kd, tid, kr);
            stV(Vd + (buf ^ 1) * (64 * 68), tid, vr);
            ryc[tid] = ryr;
        }
        __syncthreads();
    }

    // ---- epilogue ----
    #pragma unroll
    for (int r = 0; r < 8; r++) {
        int q = q0 + q0t + r;
        if (q < NQQ) {
            float inv = 1.0f / l_acc[r];
            float2 v0 = unpk2(o2[r >> 1][0]);
            float2 v1 = unpk2(o2[r >> 1][1]);
            float2 v2 = unpk2(o2[r >> 1][2]);
            float2 v3 = unpk2(o2[r >> 1][3]);
            float a = (r & 1) ? v0.y : v0.x;
            float b2 = (r & 1) ? v1.y : v1.x;
            float c = (r & 1) ? v2.y : v2.x;
            float d = (r & 1) ? v3.y : v3.x;
            *(float4*)&outp[((long long)b * NQQ + q) * EE + h * HDIM + tk * 4] =
                make_float4(a * inv, b2 * inv, c * inv, d * inv);
        }
    }
}

// ---------------------------------------------------------------------------
extern "C" void kernel_launch(void* const* d_in, const int* in_sizes, int n_in,
                              void* d_out, int out_size)
{
    const float* query = (const float*)d_in[0];
    const float* key   = (const float*)d_in[1];
    const float* value = (const float*)d_in[2];
    const float* refp  = (const float*)d_in[3];
    const float* Wq = (const float*)d_in[4];  const float* bq = (const float*)d_in[5];
    const float* Wk = (const float*)d_in[6];  const float* bk = (const float*)d_in[7];
    const float* Wv = (const float*)d_in[8];  const float* bv = (const float*)d_in[9];
    const float* Wo = (const float*)d_in[10]; const float* bo = (const float*)d_in[11];
    const float* W1x = (const float*)d_in[12]; const float* b1x = (const float*)d_in[13];
    const float* W2x = (const float*)d_in[14];
    const float* W1y = (const float*)d_in[15]; const float* b1y = (const float*)d_in[16];
    const float* W2y = (const float*)d_in[17];
    float* out = (float*)d_out;

    float *pqT, *pkT, *pv, *patt;
    cudaGetSymbolAddress((void**)&pqT, g_qT);
    cudaGetSymbolAddress((void**)&pkT, g_kT);
    cudaGetSymbolAddress((void**)&pv, g_v);
    cudaGetSymbolAddress((void**)&patt, g_att);

    static int attr_done = 0;
    if (!attr_done) {
        cudaFuncSetAttribute(attn_kernel,
                             cudaFuncAttributeMaxDynamicSharedMemorySize,
                             ATTN_SMF * 4);
        attr_done = 1;
    }

    gemm_bias_kernel<1><<<dim3(29, 4), 256>>>(query, Wq, bq, pqT, BB * NQQ,
                                              NQQ, QSCALE_F * LOG2E_F);
    gemm_bias_kernel<1><<<dim3(128, 4), 256>>>(key, Wk, bk, pkT, BB * HWK,
                                               HWK, 1.0f);
    gemm_bias_kernel<0><<<dim3(128, 4), 256>>>(value, Wv, bv, pv, BB * HWK,
                                               HWK, 1.0f);

    rpe_kernel<<<450, 256>>>(refp, W1x, b1x, W2x, W1y, b1y, W2y);

    attn_kernel<<<dim3(8, NH, BB), 128, ATTN_SMF * 4>>>(patt);

    gemm_bias_kernel<0><<<dim3(29, 4), 256>>>(patt, Wo, bo, out, BB * NQQ,
                                              NQQ, 1.0f);
}